// round 9
// baseline (speedup 1.0000x reference)
#include <cuda_runtime.h>
#include <cuda_bf16.h>
#include <math.h>
#include <stdint.h>

#define T_LEN   1024
#define DM      512
#define KF      24
#define NH      8
#define HD      64
#define BB      2
#define CHUNK   64
#define NCHUNK  (T_LEN / CHUNK)   // 16
#define NBH     (BB * NH)         // 16
#define NCAT    (5 * DM)          // 2560: Q|K|V|G|U

// ---------------- scratch (device globals; no allocation allowed) -----------
__device__ float g_phiT[DM * T_LEN];           // [r][t]
__device__ float g_upT[DM * BB * T_LEN];       // [r][b*T+t]
__device__ float g_z[BB * T_LEN * DM];
__device__ float g_xt[BB * T_LEN * DM];
__device__ float g_Q[NBH * T_LEN * HD];
__device__ float g_Kb[NBH * T_LEN * HD];
__device__ float g_V[NBH * T_LEN * HD];
__device__ float g_gate[BB * T_LEN * DM];
__device__ float g_G[NBH * NCHUNK * HD * HD];
__device__ float g_H[NBH * NCHUNK * HD * HD];
__device__ float g_Y[BB * T_LEN * DM];
__device__ float g_Wcat[NCAT * DM];            // Wq|Wk|Wv|Wg|Mi^T rows
__device__ float g_bcat[4 * DM];

// ---------------- activations ----------------------------------------------
__device__ __forceinline__ float gelu_tanh(float x) {
    const float c0 = 0.7978845608028654f;
    float inner = c0 * (x + 0.044715f * x * x * x);
    return 0.5f * x * (1.0f + tanhf(inner));
}
__device__ __forceinline__ float sigmoidf_(float x) {
    return 1.0f / (1.0f + expf(-x));
}

// ---------------- bf16 split helpers ----------------------------------------
__device__ __forceinline__ void split2(float x0, float x1, uint32_t& hp, uint32_t& lp) {
    __nv_bfloat162 h = __floats2bfloat162_rn(x0, x1);
    float r0 = x0 - __bfloat162float(__low2bfloat16(h));
    float r1 = x1 - __bfloat162float(__high2bfloat16(h));
    __nv_bfloat162 l = __floats2bfloat162_rn(r0, r1);
    hp = *reinterpret_cast<uint32_t*>(&h);
    lp = *reinterpret_cast<uint32_t*>(&l);
}

__device__ __forceinline__ void mma16(float* d, const uint32_t* a, const uint32_t* b) {
    asm volatile(
        "mma.sync.aligned.m16n8k16.row.col.f32.bf16.bf16.f32 "
        "{%0,%1,%2,%3}, {%4,%5,%6,%7}, {%8,%9}, {%0,%1,%2,%3};"
        : "+f"(d[0]), "+f"(d[1]), "+f"(d[2]), "+f"(d[3])
        : "r"(a[0]), "r"(a[1]), "r"(a[2]), "r"(a[3]), "r"(b[0]), "r"(b[1]));
}

#define LDSM4(r0, r1, r2, r3, addr)                                            \
    asm volatile("ldmatrix.sync.aligned.m8n8.x4.shared.b16 {%0,%1,%2,%3}, [%4];" \
                 : "=r"(r0), "=r"(r1), "=r"(r2), "=r"(r3) : "r"(addr))

__device__ __forceinline__ uint32_t smem_u32(const void* p) {
    return (uint32_t)__cvta_generic_to_shared(p);
}

// packed fp32x2 fma (FFMA2)
__device__ __forceinline__ uint64_t fma2(uint64_t a, uint64_t b, uint64_t c) {
    uint64_t d;
    asm("fma.rn.f32x2 %0, %1, %2, %3;" : "=l"(d) : "l"(a), "l"(b), "l"(c));
    return d;
}
__device__ __forceinline__ uint64_t bcast2(float v) {
    uint64_t d;
    uint32_t bits = __float_as_uint(v);
    asm("mov.b64 %0, {%1, %1};" : "=l"(d) : "r"(bits));
    return d;
}

// ---------------- K: phi_projT[r][t] = sum_k f[t][k] Mf[k][r] ---------------
__global__ __launch_bounds__(256) void phi_kernel(const float* __restrict__ f,
                                                  const float* __restrict__ Mf) {
    __shared__ float sf[KF];
    int t = blockIdx.x;
    if (threadIdx.x < KF) sf[threadIdx.x] = f[t * KF + threadIdx.x];
    __syncthreads();
    for (int r = threadIdx.x; r < DM; r += 256) {
        float acc = 0.f;
#pragma unroll
        for (int k = 0; k < KF; k++) acc += sf[k] * Mf[k * DM + r];
        g_phiT[(size_t)r * T_LEN + t] = acc;
    }
}

// ---------------- repack weights: Wq|Wk|Wv|Wg|Mi^T -> g_Wcat ----------------
__global__ __launch_bounds__(256) void repack_w_kernel(const float* __restrict__ Wq,
                                                       const float* __restrict__ Wk,
                                                       const float* __restrict__ Wv,
                                                       const float* __restrict__ Wg,
                                                       const float* __restrict__ Mi) {
    int i = blockIdx.x * 256 + threadIdx.x;      // 0 .. 5*2^18-1
    int seg = i >> 18;
    int off = i & ((1 << 18) - 1);
    if (seg < 4) {
        const float* W = (seg == 0) ? Wq : (seg == 1) ? Wk : (seg == 2) ? Wv : Wg;
        g_Wcat[i] = W[off];
    } else {
        int n = off >> 9, k = off & (DM - 1);
        g_Wcat[i] = Mi[(size_t)k * DM + n];      // transpose: row n of Mi^T
    }
}

// ---------------- repack biases ---------------------------------------------
__global__ __launch_bounds__(256) void repack_b_kernel(const float* __restrict__ bq,
                                                       const float* __restrict__ bk,
                                                       const float* __restrict__ bv,
                                                       const float* __restrict__ bg) {
    int i = blockIdx.x * 256 + threadIdx.x;      // 0 .. 2047
    int s2 = i >> 9, o2 = i & (DM - 1);
    const float* bp = (s2 == 0) ? bq : (s2 == 1) ? bk : (s2 == 2) ? bv : bg;
    g_bcat[i] = bp[o2];
}

// ---------------- bf16x3 tensor-core GEMM (ldmatrix fragments) ---------------
template <int EPI>
__device__ __forceinline__ void epi_store(int row, int col, float v,
                                          const float* bias, float* C, int N) {
    if (EPI == 0) {
        if (bias) v += bias[col];
        C[(size_t)row * N + col] = v;
    } else {
        int seg = col >> 9;
        if (seg == 4) {                       // u-projection, transposed
            g_upT[(size_t)(col - 4 * DM) * (BB * T_LEN) + row] = v;
            return;
        }
        v += g_bcat[col];
        int cc = col & (DM - 1);
        int b = row >> 10, t = row & (T_LEN - 1);
        if (seg == 3) {
            g_gate[(size_t)row * DM + cc] = sigmoidf_(v);
        } else {
            float gv = gelu_tanh(v);
            float* P = (seg == 0) ? g_Q : (seg == 1) ? g_Kb : g_V;
            P[(((size_t)(b * NH + (cc >> 6))) * T_LEN + t) * HD + (cc & 63)] = gv;
        }
    }
}

template <int BM, int EPI, int COMBA>
__global__ __launch_bounds__(256) void mma_gemm(const float* __restrict__ A,
                                                const float* __restrict__ B,
                                                const float* __restrict__ bias,
                                                float* __restrict__ C,
                                                int M, int N, int K) {
    constexpr int NWM = BM / 32;          // warps along M (4 or 2)
    constexpr int NT  = NWM;              // n-subtiles per warp (4 or 2)
    constexpr int S   = 20;               // padded row stride (uint32 pairs)
    __shared__ __align__(16) uint32_t sAh[BM * S];
    __shared__ __align__(16) uint32_t sAl[BM * S];
    __shared__ __align__(16) uint32_t sBh[64 * S];
    __shared__ __align__(16) uint32_t sBl[64 * S];

    const int tid = threadIdx.x;
    const int lane = tid & 31, wid = tid >> 5;
    const int wm = wid % NWM, wn = wid / NWM;
    const int brow = blockIdx.y * BM, bcol = blockIdx.x * 64;
    const int c = lane & 3, r4 = lane >> 2;

    // ldmatrix lane addresses (ks=0); ks=1 adds 32 bytes (8 words)
    uint32_t aAh0[2], aAl0[2];
#pragma unroll
    for (int mt = 0; mt < 2; mt++) {
        int row = wm * 32 + mt * 16 + (lane & 15);
        int word = (lane & 16) >> 2;           // 0 or 4
        aAh0[mt] = smem_u32(&sAh[row * S + word]);
        aAl0[mt] = smem_u32(&sAl[row * S + word]);
    }
    uint32_t aBh0[NT / 2], aBl0[NT / 2];
#pragma unroll
    for (int g = 0; g < NT / 2; g++) {
        int sel = (lane & 16) ? 1 : 0;
        int row = wn * (NT * 8) + (g * 2 + sel) * 8 + (lane & 7);
        int word = (lane & 8) ? 4 : 0;
        aBh0[g] = smem_u32(&sBh[row * S + word]);
        aBl0[g] = smem_u32(&sBl[row * S + word]);
    }

    float d[2][NT][4];
#pragma unroll
    for (int mt = 0; mt < 2; mt++)
#pragma unroll
        for (int nt = 0; nt < NT; nt++)
#pragma unroll
            for (int e = 0; e < 4; e++) d[mt][nt][e] = 0.f;

    for (int kt = 0; kt < K; kt += 32) {
        // ---- A tile: BM x 32 fp32 -> packed hi/lo pairs ----
        {
            constexpr int NF4 = BM / 32;                 // float4s per thread (4 or 2)
            int row  = (BM == 128) ? (tid >> 1) : (tid >> 2);
            int koff = (BM == 128) ? ((tid & 1) * 16) : ((tid & 3) * 8);
            uint32_t hbuf[2 * NF4], lbuf[2 * NF4];
#pragma unroll
            for (int q = 0; q < NF4; q++) {
                size_t off = (size_t)(brow + row) * K + kt + koff + q * 4;
                float4 a;
                if (COMBA) {
                    float4 gq = *reinterpret_cast<const float4*>(&g_gate[off]);
                    float4 yq = *reinterpret_cast<const float4*>(&g_Y[off]);
                    float4 xq = *reinterpret_cast<const float4*>(&g_xt[off]);
                    a.x = gq.x * yq.x + (1.f - gq.x) * xq.x;
                    a.y = gq.y * yq.y + (1.f - gq.y) * xq.y;
                    a.z = gq.z * yq.z + (1.f - gq.z) * xq.z;
                    a.w = gq.w * yq.w + (1.f - gq.w) * xq.w;
                } else {
                    a = *reinterpret_cast<const float4*>(&A[off]);
                }
                split2(a.x, a.y, hbuf[q * 2], lbuf[q * 2]);
                split2(a.z, a.w, hbuf[q * 2 + 1], lbuf[q * 2 + 1]);
            }
            int base = row * S + (koff >> 1);
#pragma unroll
            for (int q = 0; q < NF4 / 2; q++) {
                *reinterpret_cast<uint4*>(&sAh[base + q * 4]) =
                    make_uint4(hbuf[q*4], hbuf[q*4+1], hbuf[q*4+2], hbuf[q*4+3]);
                *reinterpret_cast<uint4*>(&sAl[base + q * 4]) =
                    make_uint4(lbuf[q*4], lbuf[q*4+1], lbuf[q*4+2], lbuf[q*4+3]);
            }
        }
        // ---- B tile: 64 x 32 (N x K row-major) ----
        {
            int nrow = tid >> 2, koff = (tid & 3) * 8;
            uint32_t hbuf[4], lbuf[4];
#pragma unroll
            for (int q = 0; q < 2; q++) {
                float4 w = *reinterpret_cast<const float4*>(
                    &B[(size_t)(bcol + nrow) * K + kt + koff + q * 4]);
                split2(w.x, w.y, hbuf[q * 2], lbuf[q * 2]);
                split2(w.z, w.w, hbuf[q * 2 + 1], lbuf[q * 2 + 1]);
            }
            int base = nrow * S + (koff >> 1);
            *reinterpret_cast<uint4*>(&sBh[base]) =
                make_uint4(hbuf[0], hbuf[1], hbuf[2], hbuf[3]);
            *reinterpret_cast<uint4*>(&sBl[base]) =
                make_uint4(lbuf[0], lbuf[1], lbuf[2], lbuf[3]);
        }
        __syncthreads();

#pragma unroll
        for (int ks = 0; ks < 2; ks++) {
            const uint32_t kso = ks * 32;     // 8 words = 32 bytes
            uint32_t ah[2][4], al[2][4], bh[NT][2], bl[NT][2];
#pragma unroll
            for (int mt = 0; mt < 2; mt++) {
                LDSM4(ah[mt][0], ah[mt][1], ah[mt][2], ah[mt][3], aAh0[mt] + kso);
                LDSM4(al[mt][0], al[mt][1], al[mt][2], al[mt][3], aAl0[mt] + kso);
            }
#pragma unroll
            for (int g = 0; g < NT / 2; g++) {
                LDSM4(bh[2*g][0], bh[2*g][1], bh[2*g+1][0], bh[2*g+1][1], aBh0[g] + kso);
                LDSM4(bl[2*g][0], bl[2*g][1], bl[2*g+1][0], bl[2*g+1][1], aBl0[g] + kso);
            }
#pragma unroll
            for (int mt = 0; mt < 2; mt++)
#pragma unroll
                for (int nt = 0; nt < NT; nt++) {
                    mma16(d[mt][nt], ah[mt], bh[nt]);
                    mma16(d[mt][nt], ah[mt], bl[nt]);
                    mma16(d[mt][nt], al[mt], bh[nt]);
                }
        }
        __syncthreads();
    }

    const int c2 = c * 2;
#pragma unroll
    for (int mt = 0; mt < 2; mt++) {
#pragma unroll
        for (int nt = 0; nt < NT; nt++) {
            int row0 = brow + wm * 32 + mt * 16 + r4;
            int col0 = bcol + wn * (NT * 8) + nt * 8 + c2;
            epi_store<EPI>(row0,     col0,     d[mt][nt][0], bias, C, N);
            epi_store<EPI>(row0,     col0 + 1, d[mt][nt][1], bias, C, N);
            epi_store<EPI>(row0 + 8, col0,     d[mt][nt][2], bias, C, N);
            epi_store<EPI>(row0 + 8, col0 + 1, d[mt][nt][3], bias, C, N);
        }
    }
}

// ---------------- conv: z[b,t,r] = 2 * sum_{j even<=t} v[j,r] u[b,t-j,r] ----
// Grid = DM (one r, both b per CTA). 128 threads: b = tid>>6, 16 t's/thread.
// Sliding 24-float register window + packed f32x2 FMA.
__global__ __launch_bounds__(128) void conv_kernel() {
    __shared__ __align__(16) float su[BB][T_LEN + 16];   // su[b][8+i] = u[i]
    __shared__ __align__(16) float sve[T_LEN / 2];       // sve[j/2] = v[2j]
    const int r = blockIdx.x;
    const int tid = threadIdx.x;
    const int b = tid >> 6;
    const int lt = tid & 63;
    const float* U = g_upT + (size_t)r * (BB * T_LEN) + b * T_LEN;
    const float* V = g_phiT + (size_t)r * T_LEN;
    for (int i = lt; i < T_LEN; i += 64) su[b][8 + i] = U[i];
    for (int i = tid; i < T_LEN / 2; i += 128) sve[i] = V[2 * i];
    __syncthreads();

    const int t0 = lt * 16;
    const float* sub = su[b];
    uint64_t dacc[8];
#pragma unroll
    for (int p = 0; p < 8; p++) dacc[p] = 0ull;

    const int nblk = t0 >> 3;
    if (nblk > 0) {
        uint64_t W[12];                        // pairs: W[i] = (w[2i], w[2i+1])
        int base = t0;                         // w[i] = sub[base + i]
        {
            const ulonglong2* w16 = reinterpret_cast<const ulonglong2*>(&sub[base]);
#pragma unroll
            for (int q = 0; q < 6; q++) {
                ulonglong2 u2 = w16[q];
                W[2 * q] = u2.x; W[2 * q + 1] = u2.y;
            }
        }
        for (int ib = 0; ib < nblk; ib++) {
            float4 v4 = *reinterpret_cast<const float4*>(&sve[ib * 4]);
            uint64_t vv0 = bcast2(v4.x), vv1 = bcast2(v4.y);
            uint64_t vv2 = bcast2(v4.z), vv3 = bcast2(v4.w);
#pragma unroll
            for (int p = 0; p < 8; p++) {
                dacc[p] = fma2(vv0, W[p + 4], dacc[p]);
                dacc[p] = fma2(vv1, W[p + 3], dacc[p]);
                dacc[p] = fma2(vv2, W[p + 2], dacc[p]);
                dacc[p] = fma2(vv3, W[p + 1], dacc[p]);
            }
            if (ib + 1 < nblk) {
                base -= 8;
#pragma unroll
                for (int p = 7; p >= 0; p--) W[p + 4] = W[p];
                const ulonglong2* wn = reinterpret_cast<const ulonglong2*>(&sub[base]);
                ulonglong2 a0 = wn[0], a1 = wn[1];
                W[0] = a0.x; W[1] = a0.y; W[2] = a1.x; W[3] = a1.y;
            }
        }
    }

    float acc[16];
#pragma unroll
    for (int p = 0; p < 8; p++) {
        acc[2 * p]     = __uint_as_float((uint32_t)(dacc[p] & 0xffffffffull));
        acc[2 * p + 1] = __uint_as_float((uint32_t)(dacc[p] >> 32));
    }
    // tail: j = t0 + 2*jo, jo = 0..7, active for k >= 2*jo
#pragma unroll
    for (int jo = 0; jo < 8; jo++) {
        float vj = sve[(t0 >> 1) + jo];
#pragma unroll
        for (int k = 0; k < 16; k++)
            if (k >= 2 * jo) acc[k] += vj * sub[8 + k - 2 * jo];
    }
#pragma unroll
    for (int k = 0; k < 16; k++) {
        int t = t0 + k;
        g_z[((size_t)b * T_LEN + t) * DM + r] = 2.f * acc[k];
    }
}

// ---------------- LayerNorm over last dim (512), single pass ----------------
__global__ __launch_bounds__(256) void ln_kernel(const float* __restrict__ w,
                                                 const float* __restrict__ bparm) {
    __shared__ float redA[8];
    __shared__ float redB[8];
    __shared__ float bc[2];
    int row = blockIdx.x;
    const float* xr = g_z + (size_t)row * DM;
    float v0 = xr[threadIdx.x];
    float v1 = xr[threadIdx.x + 256];
    float s1 = v0 + v1;
    float s2 = v0 * v0 + v1 * v1;
#pragma unroll
    for (int o = 16; o > 0; o >>= 1) {
        s1 += __shfl_xor_sync(0xffffffffu, s1, o);
        s2 += __shfl_xor_sync(0xffffffffu, s2, o);
    }
    int warp = threadIdx.x >> 5;
    if ((threadIdx.x & 31) == 0) { redA[warp] = s1; redB[warp] = s2; }
    __syncthreads();
    if (threadIdx.x < 32) {
        float a = (threadIdx.x < 8) ? redA[threadIdx.x] : 0.f;
        float bsum = (threadIdx.x < 8) ? redB[threadIdx.x] : 0.f;
#pragma unroll
        for (int o = 4; o > 0; o >>= 1) {
            a += __shfl_xor_sync(0xffffffffu, a, o);
            bsum += __shfl_xor_sync(0xffffffffu, bsum, o);
        }
        if (threadIdx.x == 0) { bc[0] = a; bc[1] = bsum; }
    }
    __syncthreads();
    float mu = bc[0] * (1.0f / DM);
    float var = bc[1] * (1.0f / DM) - mu * mu;
    float inv = rsqrtf(var + 1e-5f);
    float d0 = v0 - mu, d1 = v1 - mu;
    g_xt[(size_t)row * DM + threadIdx.x] = d0 * inv * w[threadIdx.x] + bparm[threadIdx.x];
    g_xt[(size_t)row * DM + threadIdx.x + 256] =
        d1 * inv * w[threadIdx.x + 256] + bparm[threadIdx.x + 256];
}

// ---------------- per-chunk state G_c = V_c^T K_c (64x64) -------------------
__global__ __launch_bounds__(256) void chunkstate_kernel() {
    __shared__ __align__(16) float sV[CHUNK * HD];
    __shared__ __align__(16) float sK[CHUNK * HD];
    int c = blockIdx.x, bh = blockIdx.y;
    const float4* Vp = reinterpret_cast<const float4*>(g_V + ((size_t)bh * T_LEN + c * CHUNK) * HD);
    const float4* Kp = reinterpret_cast<const float4*>(g_Kb + ((size_t)bh * T_LEN + c * CHUNK) * HD);
    for (int i = threadIdx.x; i < CHUNK * HD / 4; i += 256) {
        reinterpret_cast<float4*>(sV)[i] = Vp[i];
        reinterpret_cast<float4*>(sK)[i] = Kp[i];
    }
    __syncthreads();
    int p0 = (threadIdx.x >> 4) * 4, n0 = (threadIdx.x & 15) * 4;
    float acc[4][4];
#pragma unroll
    for (int i = 0; i < 4; i++)
#pragma unroll
        for (int j = 0; j < 4; j++) acc[i][j] = 0.f;
    for (int s = 0; s < CHUNK; s++) {
        float rv[4], rk[4];
#pragma unroll
        for (int i = 0; i < 4; i++) rv[i] = sV[s * HD + p0 + i];
#pragma unroll
        for (int j = 0; j < 4; j++) rk[j] = sK[s * HD + n0 + j];
#pragma unroll
        for (int i = 0; i < 4; i++)
#pragma unroll
            for (int j = 0; j < 4; j++) acc[i][j] += rv[i] * rk[j];
    }
    float* Gp = g_G + ((size_t)bh * NCHUNK + c) * HD * HD;
#pragma unroll
    for (int i = 0; i < 4; i++)
#pragma unroll
        for (int j = 0; j < 4; j++) Gp[(p0 + i) * HD + n0 + j] = acc[i][j];
}

// ---------------- exclusive prefix over chunks ------------------------------
__global__ __launch_bounds__(256) void prefix_kernel() {
    int bh = blockIdx.x;
    int base = blockIdx.y * 512;
    for (int slot = base + threadIdx.x; slot < base + 512; slot += 256) {
        float run = 0.f;
        for (int c = 0; c < NCHUNK; c++) {
            size_t idx = ((size_t)bh * NCHUNK + c) * HD * HD + slot;
            g_H[idx] = run;
            run += g_G[idx];
        }
    }
}

// ---------------- Y_c = tril(Q_c V_c^T) K_c + Q_c H_c -----------------------
__global__ __launch_bounds__(256) void attn_kernel() {
    __shared__ __align__(16) float sQ[CHUNK * HD];
    __shared__ __align__(16) float sB[CHUNK * HD];
    __shared__ __align__(16) float sS[CHUNK * CHUNK];
    int c = blockIdx.x, bh = blockIdx.y;
    int b = bh / NH, h = bh % NH;
    const float* Qp = g_Q + ((size_t)bh * T_LEN + c * CHUNK) * HD;
    const float* Vp = g_V + ((size_t)bh * T_LEN + c * CHUNK) * HD;
    const float* Kp = g_Kb + ((size_t)bh * T_LEN + c * CHUNK) * HD;

    for (int i = threadIdx.x; i < CHUNK * HD; i += 256) {
        int t = i / HD, p = i % HD;
        sQ[i] = Qp[i];
        sB[p * CHUNK + t] = Vp[i];
    }
    __syncthreads();

    int i0 = (threadIdx.x >> 4) * 4, j0 = (threadIdx.x & 15) * 4;
    float acc[4][4];
#pragma unroll
    for (int a = 0; a < 4; a++)
#pragma unroll
        for (int bb2 = 0; bb2 < 4; bb2++) acc[a][bb2] = 0.f;
    for (int p = 0; p < HD; p++) {
        float rq[4], rv[4];
#pragma unroll
        for (int a = 0; a < 4; a++) rq[a] = sQ[(i0 + a) * HD + p];
#pragma unroll
        for (int a = 0; a < 4; a++) rv[a] = sB[p * CHUNK + j0 + a];
#pragma unroll
        for (int a = 0; a < 4; a++)
#pragma unroll
            for (int bb2 = 0; bb2 < 4; bb2++) acc[a][bb2] += rq[a] * rv[bb2];
    }
#pragma unroll
    for (int a = 0; a < 4; a++)
#pragma unroll
        for (int bb2 = 0; bb2 < 4; bb2++)
            sS[(i0 + a) * CHUNK + j0 + bb2] = (j0 + bb2 <= i0 + a) ? acc[a][bb2] : 0.f;
    __syncthreads();

    for (int i = threadIdx.x; i < CHUNK * HD; i += 256) sB[i] = Kp[i];
    __syncthreads();

    float acc2[4][4];
#pragma unroll
    for (int a = 0; a < 4; a++)
#pragma unroll
        for (int bb2 = 0; bb2 < 4; bb2++) acc2[a][bb2] = 0.f;
    for (int j = 0; j < CHUNK; j++) {
        float rs[4], rk[4];
#pragma unroll
        for (int a = 0; a < 4; a++) rs[a] = sS[(i0 + a) * CHUNK + j];
#pragma unroll
        for (int a = 0; a < 4; a++) rk[a] = sB[j * HD + j0 + a];
#pragma unroll
        for (int a = 0; a < 4; a++)
#pragma unroll
            for (int bb2 = 0; bb2 < 4; bb2++) acc2[a][bb2] += rs[a] * rk[bb2];
    }
    const float* Hp = g_H + ((size_t)bh * NCHUNK + c) * HD * HD;
    for (int p = 0; p < HD; p++) {
        float rq[4], rh[4];
#pragma unroll
        for (int a = 0; a < 4; a++) rq[a] = sQ[(i0 + a) * HD + p];
#pragma unroll
        for (int a = 0; a < 4; a++) rh[a] = Hp[p * HD + j0 + a];
#pragma unroll
        for (int a = 0; a < 4; a++)
#pragma unroll
            for (int bb2 = 0; bb2 < 4; bb2++) acc2[a][bb2] += rq[a] * rh[bb2];
    }
#pragma unroll
    for (int a = 0; a < 4; a++) {
        int t = c * CHUNK + i0 + a;
#pragma unroll
        for (int bb2 = 0; bb2 < 4; bb2++)
            g_Y[((size_t)b * T_LEN + t) * DM + h * HD + j0 + bb2] = acc2[a][bb2];
    }
}

// ---------------- host launcher ---------------------------------------------
extern "C" void kernel_launch(void* const* d_in, const int* in_sizes, int n_in,
                              void* d_out, int out_size) {
    const float* x   = (const float*)d_in[0];
    const float* flt = (const float*)d_in[1];
    const float* Mi  = (const float*)d_in[2];
    const float* Mf  = (const float*)d_in[3];
    const float* Wq  = (const float*)d_in[4];
    const float* bq  = (const float*)d_in[5];
    const float* Wk  = (const float*)d_in[6];
    const float* bk  = (const float*)d_in[7];
    const float* Wv  = (const float*)d_in[8];
    const float* bv  = (const float*)d_in[9];
    const float* Wg  = (const float*)d_in[10];
    const float* bg  = (const float*)d_in[11];
    const float* Wo  = (const float*)d_in[12];
    const float* bo  = (const float*)d_in[13];
    const float* lnw = (const float*)d_in[14];
    const float* lnb = (const float*)d_in[15];
    float* out = (float*)d_out;

    float* Wcat;
    cudaGetSymbolAddress((void**)&Wcat, g_Wcat);

    const int M = BB * T_LEN;  // 2048

    // 1-3: preprocessing
    repack_w_kernel<<<NCAT * DM / 256, 256>>>(Wq, Wk, Wv, Wg, Mi);
    repack_b_kernel<<<4 * DM / 256, 256>>>(bq, bk, bv, bg);
    phi_kernel<<<T_LEN, 256>>>(flt, Mf);

    // 4: fused Q|K|V|G|U projection (N = 2560)  [profiled slot]
    mma_gemm<128, 1, 0><<<dim3(NCAT / 64, M / 128), 256>>>(x, Wcat, nullptr, nullptr,
                                                           M, NCAT, DM);

    // 5-6: STU conv + layernorm
    conv_kernel<<<DM, 128>>>();
    ln_kernel<<<M, 256>>>(lnw, lnb);

    // 7-9: chunked linear attention
    chunkstate_kernel<<<dim3(NCHUNK, NBH), 256>>>();
    prefix_kernel<<<dim3(NBH, 8), 256>>>();
    attn_kernel<<<dim3(NCHUNK, NBH), 256>>>();

    // 10: output projection with fused combine, BM=64 tiles (256 CTAs)
    mma_gemm<64, 0, 1><<<dim3(DM / 64, M / 64), 256>>>(nullptr, Wo, bo, out,
                                                       M, DM, DM);
}

// round 11
// speedup vs baseline: 1.0173x; 1.0173x over previous
#include <cuda_runtime.h>
#include <cuda_bf16.h>
#include <math.h>
#include <stdint.h>

#define T_LEN   1024
#define DM      512
#define KF      24
#define NH      8
#define HD      64
#define BB      2
#define CHUNK   64
#define NCHUNK  (T_LEN / CHUNK)   // 16
#define NBH     (BB * NH)         // 16
#define NCAT    (5 * DM)          // 2560: Q|K|V|G|U
#define NWROWS  (NCAT + DM)       // 3072: + Wo
#define KW      (DM / 2)          // 256 packed words per row

// ---------------- scratch (device globals; no allocation allowed) -----------
__device__ float g_phiT[DM * T_LEN];           // [r][t]
__device__ float g_upT[DM * BB * T_LEN];       // [r][b*T+t]
__device__ float g_z[BB * T_LEN * DM];
__device__ float g_xt[BB * T_LEN * DM];
__device__ float g_Q[NBH * T_LEN * HD];
__device__ float g_Kb[NBH * T_LEN * HD];
__device__ float g_V[NBH * T_LEN * HD];
__device__ float g_gate[BB * T_LEN * DM];
__device__ float g_G[NBH * NCHUNK * HD * HD];
__device__ float g_H[NBH * NCHUNK * HD * HD];
__device__ float g_Y[BB * T_LEN * DM];
__device__ float g_bcat[4 * DM];
// packed bf16 hi/lo operands (word = bf16x2, k-pairs)
__device__ uint32_t g_Ah[BB * T_LEN * KW];     // A operand (x, later comb)
__device__ uint32_t g_Al[BB * T_LEN * KW];
__device__ uint32_t g_Wh[NWROWS * KW];         // Wq|Wk|Wv|Wg|Mi^T|Wo
__device__ uint32_t g_Wl[NWROWS * KW];

// ---------------- activations ----------------------------------------------
__device__ __forceinline__ float gelu_tanh(float x) {
    const float c0 = 0.7978845608028654f;
    float inner = c0 * (x + 0.044715f * x * x * x);
    return 0.5f * x * (1.0f + tanhf(inner));
}
__device__ __forceinline__ float sigmoidf_(float x) {
    return 1.0f / (1.0f + expf(-x));
}

// ---------------- bf16 split helpers ----------------------------------------
__device__ __forceinline__ void split2(float x0, float x1, uint32_t& hp, uint32_t& lp) {
    __nv_bfloat162 h = __floats2bfloat162_rn(x0, x1);
    float r0 = x0 - __bfloat162float(__low2bfloat16(h));
    float r1 = x1 - __bfloat162float(__high2bfloat16(h));
    __nv_bfloat162 l = __floats2bfloat162_rn(r0, r1);
    hp = *reinterpret_cast<uint32_t*>(&h);
    lp = *reinterpret_cast<uint32_t*>(&l);
}

__device__ __forceinline__ void mma16(float* d, const uint32_t* a, const uint32_t* b) {
    asm volatile(
        "mma.sync.aligned.m16n8k16.row.col.f32.bf16.bf16.f32 "
        "{%0,%1,%2,%3}, {%4,%5,%6,%7}, {%8,%9}, {%0,%1,%2,%3};"
        : "+f"(d[0]), "+f"(d[1]), "+f"(d[2]), "+f"(d[3])
        : "r"(a[0]), "r"(a[1]), "r"(a[2]), "r"(a[3]), "r"(b[0]), "r"(b[1]));
}

#define LDSM4(r0, r1, r2, r3, addr)                                            \
    asm volatile("ldmatrix.sync.aligned.m8n8.x4.shared.b16 {%0,%1,%2,%3}, [%4];" \
                 : "=r"(r0), "=r"(r1), "=r"(r2), "=r"(r3) : "r"(addr))

__device__ __forceinline__ uint32_t smem_u32(const void* p) {
    return (uint32_t)__cvta_generic_to_shared(p);
}

// packed fp32x2 fma (FFMA2)
__device__ __forceinline__ uint64_t fma2(uint64_t a, uint64_t b, uint64_t c) {
    uint64_t d;
    asm("fma.rn.f32x2 %0, %1, %2, %3;" : "=l"(d) : "l"(a), "l"(b), "l"(c));
    return d;
}
__device__ __forceinline__ uint64_t bcast2(float v) {
    uint64_t d;
    uint32_t bits = __float_as_uint(v);
    asm("mov.b64 %0, {%1, %1};" : "=l"(d) : "r"(bits));
    return d;
}

// ---------------- xsplit: x -> g_Ah/g_Al -------------------------------------
__global__ __launch_bounds__(256) void xsplit_kernel(const float* __restrict__ x) {
    int i = blockIdx.x * 256 + threadIdx.x;        // word index
    float2 v = reinterpret_cast<const float2*>(x)[i];
    uint32_t h, l;
    split2(v.x, v.y, h, l);
    g_Ah[i] = h;
    g_Al[i] = l;
}

// ---------------- repack+split weights: Wq|Wk|Wv|Wg|Mi^T|Wo -----------------
__global__ __launch_bounds__(256) void repack_w_kernel(const float* __restrict__ Wq,
                                                       const float* __restrict__ Wk,
                                                       const float* __restrict__ Wv,
                                                       const float* __restrict__ Wg,
                                                       const float* __restrict__ Mi,
                                                       const float* __restrict__ Wo) {
    int i = blockIdx.x * 256 + threadIdx.x;        // word index, 0..NWROWS*KW-1
    int n = i >> 8;                                // row 0..3071
    int p = i & 255;
    int k = p * 2;
    int seg = n >> 9, nn = n & (DM - 1);
    float a0, a1;
    if (seg == 4) {                                // Mi^T: row nn of Mi transpose
        a0 = Mi[(size_t)k * DM + nn];
        a1 = Mi[(size_t)(k + 1) * DM + nn];
    } else {
        const float* W = (seg == 0) ? Wq : (seg == 1) ? Wk : (seg == 2) ? Wv
                        : (seg == 3) ? Wg : Wo;
        float2 v = *reinterpret_cast<const float2*>(&W[(size_t)nn * DM + k]);
        a0 = v.x; a1 = v.y;
    }
    uint32_t h, l;
    split2(a0, a1, h, l);
    g_Wh[i] = h;
    g_Wl[i] = l;
}

// ---------------- repack biases ---------------------------------------------
__global__ __launch_bounds__(256) void repack_b_kernel(const float* __restrict__ bq,
                                                       const float* __restrict__ bk,
                                                       const float* __restrict__ bv,
                                                       const float* __restrict__ bg) {
    int i = blockIdx.x * 256 + threadIdx.x;      // 0 .. 2047
    int s2 = i >> 9, o2 = i & (DM - 1);
    const float* bp = (s2 == 0) ? bq : (s2 == 1) ? bk : (s2 == 2) ? bv : bg;
    g_bcat[i] = bp[o2];
}

// ---------------- phi_projT[r][t] = sum_k f[t][k] Mf[k][r] ------------------
__global__ __launch_bounds__(256) void phi_kernel(const float* __restrict__ f,
                                                  const float* __restrict__ Mf) {
    __shared__ float sf[KF];
    int t = blockIdx.x;
    if (threadIdx.x < KF) sf[threadIdx.x] = f[t * KF + threadIdx.x];
    __syncthreads();
    for (int r = threadIdx.x; r < DM; r += 256) {
        float acc = 0.f;
#pragma unroll
        for (int k = 0; k < KF; k++) acc += sf[k] * Mf[k * DM + r];
        g_phiT[(size_t)r * T_LEN + t] = acc;
    }
}

// ---------------- combine + split: comb = g*Y + (1-g)*xt -> g_Ah/g_Al -------
__global__ __launch_bounds__(256) void combsplit_kernel() {
    int i = blockIdx.x * 256 + threadIdx.x;        // word index
    float2 g = *reinterpret_cast<const float2*>(&g_gate[2 * i]);
    float2 y = *reinterpret_cast<const float2*>(&g_Y[2 * i]);
    float2 xt = *reinterpret_cast<const float2*>(&g_xt[2 * i]);
    float c0 = g.x * y.x + (1.f - g.x) * xt.x;
    float c1 = g.y * y.y + (1.f - g.y) * xt.y;
    uint32_t h, l;
    split2(c0, c1, h, l);
    g_Ah[i] = h;
    g_Al[i] = l;
}

// ---------------- bf16x3 tensor-core GEMM (pre-split operands) ---------------
// C(MxN) = A @ B^T with A = g_Ah/g_Al (M x 512), B rows packed in Bh/Bl.
// EPI 0: C + optional bias. EPI 1: fused QKVG scatter + U transposed.
template <int EPI>
__device__ __forceinline__ void epi_store(int row, int col, float v,
                                          const float* bias, float* C, int N) {
    if (EPI == 0) {
        if (bias) v += bias[col];
        C[(size_t)row * N + col] = v;
    } else {
        int seg = col >> 9;
        if (seg == 4) {                       // u-projection, transposed
            g_upT[(size_t)(col - 4 * DM) * (BB * T_LEN) + row] = v;
            return;
        }
        v += g_bcat[col];
        int cc = col & (DM - 1);
        int b = row >> 10, t = row & (T_LEN - 1);
        if (seg == 3) {
            g_gate[(size_t)row * DM + cc] = sigmoidf_(v);
        } else {
            float gv = gelu_tanh(v);
            float* P = (seg == 0) ? g_Q : (seg == 1) ? g_Kb : g_V;
            P[(((size_t)(b * NH + (cc >> 6))) * T_LEN + t) * HD + (cc & 63)] = gv;
        }
    }
}

template <int BM, int EPI>
__global__ __launch_bounds__(256) void mma_gemm(const uint32_t* __restrict__ Bh,
                                                const uint32_t* __restrict__ Bl,
                                                const float* __restrict__ bias,
                                                float* __restrict__ C,
                                                int M, int N) {
    constexpr int NWM = BM / 32;          // warps along M (4 or 2)
    constexpr int NT  = NWM;              // n-subtiles per warp (4 or 2)
    constexpr int S   = 20;               // padded row stride (words)
    __shared__ __align__(16) uint32_t sAh[BM * S];
    __shared__ __align__(16) uint32_t sAl[BM * S];
    __shared__ __align__(16) uint32_t sBh[64 * S];
    __shared__ __align__(16) uint32_t sBl[64 * S];

    const int tid = threadIdx.x;
    const int lane = tid & 31, wid = tid >> 5;
    const int wm = wid % NWM, wn = wid / NWM;
    const int brow = blockIdx.y * BM, bcol = blockIdx.x * 64;
    const int c = lane & 3, r4 = lane >> 2;

    // ldmatrix lane addresses (ks=0); ks=1 adds 32 bytes (8 words)
    uint32_t aAh0[2], aAl0[2];
#pragma unroll
    for (int mt = 0; mt < 2; mt++) {
        int row = wm * 32 + mt * 16 + (lane & 15);
        int word = (lane & 16) >> 2;           // 0 or 4
        aAh0[mt] = smem_u32(&sAh[row * S + word]);
        aAl0[mt] = smem_u32(&sAl[row * S + word]);
    }
    uint32_t aBh0[NT / 2], aBl0[NT / 2];
#pragma unroll
    for (int g = 0; g < NT / 2; g++) {
        int sel = (lane & 16) ? 1 : 0;
        int row = wn * (NT * 8) + (g * 2 + sel) * 8 + (lane & 7);
        int word = (lane & 8) ? 4 : 0;
        aBh0[g] = smem_u32(&sBh[row * S + word]);
        aBl0[g] = smem_u32(&sBl[row * S + word]);
    }

    float d[2][NT][4];
#pragma unroll
    for (int mt = 0; mt < 2; mt++)
#pragma unroll
        for (int nt = 0; nt < NT; nt++)
#pragma unroll
            for (int e = 0; e < 4; e++) d[mt][nt][e] = 0.f;

    for (int ktw = 0; ktw < KW; ktw += 16) {
        // ---- A tile: BM x 16 words from g_Ah/g_Al ----
        if (BM == 128) {
            int row = tid >> 1, h8 = (tid & 1) * 8;
            size_t src = (size_t)(brow + row) * KW + ktw + h8;
            uint4 h0 = *reinterpret_cast<const uint4*>(&g_Ah[src]);
            uint4 h1 = *reinterpret_cast<const uint4*>(&g_Ah[src + 4]);
            uint4 l0 = *reinterpret_cast<const uint4*>(&g_Al[src]);
            uint4 l1 = *reinterpret_cast<const uint4*>(&g_Al[src + 4]);
            int base = row * S + h8;
            *reinterpret_cast<uint4*>(&sAh[base]) = h0;
            *reinterpret_cast<uint4*>(&sAh[base + 4]) = h1;
            *reinterpret_cast<uint4*>(&sAl[base]) = l0;
            *reinterpret_cast<uint4*>(&sAl[base + 4]) = l1;
        } else {
            int row = tid >> 2, q4 = (tid & 3) * 4;
            size_t src = (size_t)(brow + row) * KW + ktw + q4;
            uint4 h0 = *reinterpret_cast<const uint4*>(&g_Ah[src]);
            uint4 l0 = *reinterpret_cast<const uint4*>(&g_Al[src]);
            *reinterpret_cast<uint4*>(&sAh[row * S + q4]) = h0;
            *reinterpret_cast<uint4*>(&sAl[row * S + q4]) = l0;
        }
        // ---- B tile: 64 x 16 words from Bh/Bl ----
        {
            int row = tid >> 2, q4 = (tid & 3) * 4;
            size_t src = (size_t)(bcol + row) * KW + ktw + q4;
            uint4 h0 = *reinterpret_cast<const uint4*>(&Bh[src]);
            uint4 l0 = *reinterpret_cast<const uint4*>(&Bl[src]);
            *reinterpret_cast<uint4*>(&sBh[row * S + q4]) = h0;
            *reinterpret_cast<uint4*>(&sBl[row * S + q4]) = l0;
        }
        __syncthreads();

#pragma unroll
        for (int ks = 0; ks < 2; ks++) {
            const uint32_t kso = ks * 32;     // 8 words = 32 bytes
            uint32_t ah[2][4], al[2][4], bh[NT][2], bl[NT][2];
#pragma unroll
            for (int mt = 0; mt < 2; mt++) {
                LDSM4(ah[mt][0], ah[mt][1], ah[mt][2], ah[mt][3], aAh0[mt] + kso);
                LDSM4(al[mt][0], al[mt][1], al[mt][2], al[mt][3], aAl0[mt] + kso);
            }
#pragma unroll
            for (int g = 0; g < NT / 2; g++) {
                LDSM4(bh[2*g][0], bh[2*g][1], bh[2*g+1][0], bh[2*g+1][1], aBh0[g] + kso);
                LDSM4(bl[2*g][0], bl[2*g][1], bl[2*g+1][0], bl[2*g+1][1], aBl0[g] + kso);
            }
#pragma unroll
            for (int mt = 0; mt < 2; mt++)
#pragma unroll
                for (int nt = 0; nt < NT; nt++) {
                    mma16(d[mt][nt], ah[mt], bh[nt]);
                    mma16(d[mt][nt], ah[mt], bl[nt]);
                    mma16(d[mt][nt], al[mt], bh[nt]);
                }
        }
        __syncthreads();
    }

    const int c2 = c * 2;
#pragma unroll
    for (int mt = 0; mt < 2; mt++) {
#pragma unroll
        for (int nt = 0; nt < NT; nt++) {
            int row0 = brow + wm * 32 + mt * 16 + r4;
            int col0 = bcol + wn * (NT * 8) + nt * 8 + c2;
            epi_store<EPI>(row0,     col0,     d[mt][nt][0], bias, C, N);
            epi_store<EPI>(row0,     col0 + 1, d[mt][nt][1], bias, C, N);
            epi_store<EPI>(row0 + 8, col0,     d[mt][nt][2], bias, C, N);
            epi_store<EPI>(row0 + 8, col0 + 1, d[mt][nt][3], bias, C, N);
        }
    }
}

// ---------------- conv: z[b,t,r] = 2 * sum_{j even<=t} v[j,r] u[b,t-j,r] ----
__global__ __launch_bounds__(128) void conv_kernel() {
    __shared__ __align__(16) float su[BB][T_LEN + 16];   // su[b][8+i] = u[i]
    __shared__ __align__(16) float sve[T_LEN / 2];       // sve[j/2] = v[2j]
    const int r = blockIdx.x;
    const int tid = threadIdx.x;
    const int b = tid >> 6;
    const int lt = tid & 63;
    const float* U = g_upT + (size_t)r * (BB * T_LEN) + b * T_LEN;
    const float* V = g_phiT + (size_t)r * T_LEN;
    for (int i = lt; i < T_LEN; i += 64) su[b][8 + i] = U[i];
    for (int i = tid; i < T_LEN / 2; i += 128) sve[i] = V[2 * i];
    __syncthreads();

    const int t0 = lt * 16;
    const float* sub = su[b];
    uint64_t dacc[8];
#pragma unroll
    for (int p = 0; p < 8; p++) dacc[p] = 0ull;

    const int nblk = t0 >> 3;
    if (nblk > 0) {
        uint64_t W[12];
        int base = t0;
        {
            const ulonglong2* w16 = reinterpret_cast<const ulonglong2*>(&sub[base]);
#pragma unroll
            for (int q = 0; q < 6; q++) {
                ulonglong2 u2 = w16[q];
                W[2 * q] = u2.x; W[2 * q + 1] = u2.y;
            }
        }
        for (int ib = 0; ib < nblk; ib++) {
            float4 v4 = *reinterpret_cast<const float4*>(&sve[ib * 4]);
            uint64_t vv0 = bcast2(v4.x), vv1 = bcast2(v4.y);
            uint64_t vv2 = bcast2(v4.z), vv3 = bcast2(v4.w);
#pragma unroll
            for (int p = 0; p < 8; p++) {
                dacc[p] = fma2(vv0, W[p + 4], dacc[p]);
                dacc[p] = fma2(vv1, W[p + 3], dacc[p]);
                dacc[p] = fma2(vv2, W[p + 2], dacc[p]);
                dacc[p] = fma2(vv3, W[p + 1], dacc[p]);
            }
            if (ib + 1 < nblk) {
                base -= 8;
#pragma unroll
                for (int p = 7; p >= 0; p--) W[p + 4] = W[p];
                const ulonglong2* wn = reinterpret_cast<const ulonglong2*>(&sub[base]);
                ulonglong2 a0 = wn[0], a1 = wn[1];
                W[0] = a0.x; W[1] = a0.y; W[2] = a1.x; W[3] = a1.y;
            }
        }
    }

    float acc[16];
#pragma unroll
    for (int p = 0; p < 8; p++) {
        acc[2 * p]     = __uint_as_float((uint32_t)(dacc[p] & 0xffffffffull));
        acc[2 * p + 1] = __uint_as_float((uint32_t)(dacc[p] >> 32));
    }
#pragma unroll
    for (int jo = 0; jo < 8; jo++) {
        float vj = sve[(t0 >> 1) + jo];
#pragma unroll
        for (int k = 0; k < 16; k++)
            if (k >= 2 * jo) acc[k] += vj * sub[8 + k - 2 * jo];
    }
#pragma unroll
    for (int k = 0; k < 16; k++) {
        int t = t0 + k;
        g_z[((size_t)b * T_LEN + t) * DM + r] = 2.f * acc[k];
    }
}

// ---------------- LayerNorm over last dim (512), single pass ----------------
__global__ __launch_bounds__(256) void ln_kernel(const float* __restrict__ w,
                                                 const float* __restrict__ bparm) {
    __shared__ float redA[8];
    __shared__ float redB[8];
    __shared__ float bc[2];
    int row = blockIdx.x;
    const float* xr = g_z + (size_t)row * DM;
    float v0 = xr[threadIdx.x];
    float v1 = xr[threadIdx.x + 256];
    float s1 = v0 + v1;
    float s2 = v0 * v0 + v1 * v1;
#pragma unroll
    for (int o = 16; o > 0; o >>= 1) {
        s1 += __shfl_xor_sync(0xffffffffu, s1, o);
        s2 += __shfl_xor_sync(0xffffffffu, s2, o);
    }
    int warp = threadIdx.x >> 5;
    if ((threadIdx.x & 31) == 0) { redA[warp] = s1; redB[warp] = s2; }
    __syncthreads();
    if (threadIdx.x < 32) {
        float a = (threadIdx.x < 8) ? redA[threadIdx.x] : 0.f;
        float bsum = (threadIdx.x < 8) ? redB[threadIdx.x] : 0.f;
#pragma unroll
        for (int o = 4; o > 0; o >>= 1) {
            a += __shfl_xor_sync(0xffffffffu, a, o);
            bsum += __shfl_xor_sync(0xffffffffu, bsum, o);
        }
        if (threadIdx.x == 0) { bc[0] = a; bc[1] = bsum; }
    }
    __syncthreads();
    float mu = bc[0] * (1.0f / DM);
    float var = bc[1] * (1.0f / DM) - mu * mu;
    float inv = rsqrtf(var + 1e-5f);
    float d0 = v0 - mu, d1 = v1 - mu;
    g_xt[(size_t)row * DM + threadIdx.x] = d0 * inv * w[threadIdx.x] + bparm[threadIdx.x];
    g_xt[(size_t)row * DM + threadIdx.x + 256] =
        d1 * inv * w[threadIdx.x + 256] + bparm[threadIdx.x + 256];
}

// ---------------- per-chunk state G_c = V_c^T K_c (64x64) -------------------
__global__ __launch_bounds__(256) void chunkstate_kernel() {
    __shared__ __align__(16) float sV[CHUNK * HD];
    __shared__ __align__(16) float sK[CHUNK * HD];
    int c = blockIdx.x, bh = blockIdx.y;
    const float4* Vp = reinterpret_cast<const float4*>(g_V + ((size_t)bh * T_LEN + c * CHUNK) * HD);
    const float4* Kp = reinterpret_cast<const float4*>(g_Kb + ((size_t)bh * T_LEN + c * CHUNK) * HD);
    for (int i = threadIdx.x; i < CHUNK * HD / 4; i += 256) {
        reinterpret_cast<float4*>(sV)[i] = Vp[i];
        reinterpret_cast<float4*>(sK)[i] = Kp[i];
    }
    __syncthreads();
    int p0 = (threadIdx.x >> 4) * 4, n0 = (threadIdx.x & 15) * 4;
    float acc[4][4];
#pragma unroll
    for (int i = 0; i < 4; i++)
#pragma unroll
        for (int j = 0; j < 4; j++) acc[i][j] = 0.f;
    for (int s = 0; s < CHUNK; s++) {
        float rv[4], rk[4];
#pragma unroll
        for (int i = 0; i < 4; i++) rv[i] = sV[s * HD + p0 + i];
#pragma unroll
        for (int j = 0; j < 4; j++) rk[j] = sK[s * HD + n0 + j];
#pragma unroll
        for (int i = 0; i < 4; i++)
#pragma unroll
            for (int j = 0; j < 4; j++) acc[i][j] += rv[i] * rk[j];
    }
    float* Gp = g_G + ((size_t)bh * NCHUNK + c) * HD * HD;
#pragma unroll
    for (int i = 0; i < 4; i++)
#pragma unroll
        for (int j = 0; j < 4; j++) Gp[(p0 + i) * HD + n0 + j] = acc[i][j];
}

// ---------------- exclusive prefix over chunks ------------------------------
__global__ __launch_bounds__(256) void prefix_kernel() {
    int bh = blockIdx.x;
    int base = blockIdx.y * 512;
    for (int slot = base + threadIdx.x; slot < base + 512; slot += 256) {
        float run = 0.f;
        for (int c = 0; c < NCHUNK; c++) {
            size_t idx = ((size_t)bh * NCHUNK + c) * HD * HD + slot;
            g_H[idx] = run;
            run += g_G[idx];
        }
    }
}

// ---------------- Y_c = tril(Q_c V_c^T) K_c + Q_c H_c -----------------------
__global__ __launch_bounds__(256) void attn_kernel() {
    __shared__ __align__(16) float sQ[CHUNK * HD];
    __shared__ __align__(16) float sB[CHUNK * HD];
    __shared__ __align__(16) float sS[CHUNK * CHUNK];
    int c = blockIdx.x, bh = blockIdx.y;
    int b = bh / NH, h = bh % NH;
    const float* Qp = g_Q + ((size_t)bh * T_LEN + c * CHUNK) * HD;
    const float* Vp = g_V + ((size_t)bh * T_LEN + c * CHUNK) * HD;
    const float* Kp = g_Kb + ((size_t)bh * T_LEN + c * CHUNK) * HD;

    for (int i = threadIdx.x; i < CHUNK * HD; i += 256) {
        int t = i / HD, p = i % HD;
        sQ[i] = Qp[i];
        sB[p * CHUNK + t] = Vp[i];
    }
    __syncthreads();

    int i0 = (threadIdx.x >> 4) * 4, j0 = (threadIdx.x & 15) * 4;
    float acc[4][4];
#pragma unroll
    for (int a = 0; a < 4; a++)
#pragma unroll
        for (int bb2 = 0; bb2 < 4; bb2++) acc[a][bb2] = 0.f;
    for (int p = 0; p < HD; p++) {
        float rq[4], rv[4];
#pragma unroll
        for (int a = 0; a < 4; a++) rq[a] = sQ[(i0 + a) * HD + p];
#pragma unroll
        for (int a = 0; a < 4; a++) rv[a] = sB[p * CHUNK + j0 + a];
#pragma unroll
        for (int a = 0; a < 4; a++)
#pragma unroll
            for (int bb2 = 0; bb2 < 4; bb2++) acc[a][bb2] += rq[a] * rv[bb2];
    }
#pragma unroll
    for (int a = 0; a < 4; a++)
#pragma unroll
        for (int bb2 = 0; bb2 < 4; bb2++)
            sS[(i0 + a) * CHUNK + j0 + bb2] = (j0 + bb2 <= i0 + a) ? acc[a][bb2] : 0.f;
    __syncthreads();

    for (int i = threadIdx.x; i < CHUNK * HD; i += 256) sB[i] = Kp[i];
    __syncthreads();

    float acc2[4][4];
#pragma unroll
    for (int a = 0; a < 4; a++)
#pragma unroll
        for (int bb2 = 0; bb2 < 4; bb2++) acc2[a][bb2] = 0.f;
    for (int j = 0; j < CHUNK; j++) {
        float rs[4], rk[4];
#pragma unroll
        for (int a = 0; a < 4; a++) rs[a] = sS[(i0 + a) * CHUNK + j];
#pragma unroll
        for (int a = 0; a < 4; a++) rk[a] = sB[j * HD + j0 + a];
#pragma unroll
        for (int a = 0; a < 4; a++)
#pragma unroll
            for (int bb2 = 0; bb2 < 4; bb2++) acc2[a][bb2] += rs[a] * rk[bb2];
    }
    const float* Hp = g_H + ((size_t)bh * NCHUNK + c) * HD * HD;
    for (int p = 0; p < HD; p++) {
        float rq[4], rh[4];
#pragma unroll
        for (int a = 0; a < 4; a++) rq[a] = sQ[(i0 + a) * HD + p];
#pragma unroll
        for (int a = 0; a < 4; a++) rh[a] = Hp[p * HD + j0 + a];
#pragma unroll
        for (int a = 0; a < 4; a++)
#pragma unroll
            for (int bb2 = 0; bb2 < 4; bb2++) acc2[a][bb2] += rq[a] * rh[bb2];
    }
#pragma unroll
    for (int a = 0; a < 4; a++) {
        int t = c * CHUNK + i0 + a;
#pragma unroll
        for (int bb2 = 0; bb2 < 4; bb2++)
            g_Y[((size_t)b * T_LEN + t) * DM + h * HD + j0 + bb2] = acc2[a][bb2];
    }
}

// ---------------- host launcher ---------------------------------------------
extern "C" void kernel_launch(void* const* d_in, const int* in_sizes, int n_in,
                              void* d_out, int out_size) {
    const float* x   = (const float*)d_in[0];
    const float* flt = (const float*)d_in[1];
    const float* Mi  = (const float*)d_in[2];
    const float* Mf  = (const float*)d_in[3];
    const float* Wq  = (const float*)d_in[4];
    const float* bq  = (const float*)d_in[5];
    const float* Wk  = (const float*)d_in[6];
    const float* bk  = (const float*)d_in[7];
    const float* Wv  = (const float*)d_in[8];
    const float* bv  = (const float*)d_in[9];
    const float* Wg  = (const float*)d_in[10];
    const float* bg  = (const float*)d_in[11];
    const float* Wo  = (const float*)d_in[12];
    const float* bo  = (const float*)d_in[13];
    const float* lnw = (const float*)d_in[14];
    const float* lnb = (const float*)d_in[15];
    float* out = (float*)d_out;

    uint32_t *Wh, *Wl;
    cudaGetSymbolAddress((void**)&Wh, g_Wh);
    cudaGetSymbolAddress((void**)&Wl, g_Wl);

    const int M = BB * T_LEN;  // 2048

    // 1-3: operand preparation (split once)
    xsplit_kernel<<<M * KW / 256, 256>>>(x);
    repack_w_kernel<<<NWROWS * KW / 256, 256>>>(Wq, Wk, Wv, Wg, Mi, Wo);
    repack_b_kernel<<<4 * DM / 256, 256>>>(bq, bk, bv, bg);

    // 4: fused Q|K|V|G|U projection (N = 2560)  [profiled slot]
    mma_gemm<128, 1><<<dim3(NCAT / 64, M / 128), 256>>>(Wh, Wl, nullptr, nullptr,
                                                        M, NCAT);

    // 5-7: STU branch
    phi_kernel<<<T_LEN, 256>>>(flt, Mf);
    conv_kernel<<<DM, 128>>>();
    ln_kernel<<<M, 256>>>(lnw, lnb);

    // 8-10: chunked linear attention
    chunkstate_kernel<<<dim3(NCHUNK, NBH), 256>>>();
    prefix_kernel<<<dim3(NBH, 8), 256>>>();
    attn_kernel<<<dim3(NCHUNK, NBH), 256>>>();

    // 11: combine + split into A buffers
    combsplit_kernel<<<M * KW / 256, 256>>>();

    // 12: output projection (B = Wo rows at offset NCAT)
    mma_gemm<64, 0><<<dim3(DM / 64, M / 64), 256>>>(Wh + (size_t)NCAT * KW,
                                                    Wl + (size_t)NCAT * KW,
                                                    bo, out, M, DM);
}

// round 13
// speedup vs baseline: 1.0803x; 1.0619x over previous
#include <cuda_runtime.h>
#include <cuda_bf16.h>
#include <math.h>
#include <stdint.h>

#define T_LEN   1024
#define DM      512
#define KF      24
#define NH      8
#define HD      64
#define BB      2
#define CHUNK   64
#define NCHUNK  (T_LEN / CHUNK)   // 16
#define NBH     (BB * NH)         // 16
#define NCAT    (5 * DM)          // 2560: Q|K|V|G|U
#define NWROWS  (NCAT + DM)       // 3072: + Wo
#define KW      (DM / 2)          // 256 packed words per row

// ---------------- scratch (device globals; no allocation allowed) -----------
__device__ float g_phiT[DM * T_LEN];           // [r][t]
__device__ float g_upT[DM * BB * T_LEN];       // [r][b*T+t]
__device__ float g_z[BB * T_LEN * DM];
__device__ float g_xt[BB * T_LEN * DM];
__device__ float g_Q[NBH * T_LEN * HD];
__device__ float g_Kb[NBH * T_LEN * HD];
__device__ float g_V[NBH * T_LEN * HD];
__device__ float g_gate[BB * T_LEN * DM];
__device__ float g_G[NBH * NCHUNK * HD * HD];
__device__ float g_H[NBH * NCHUNK * HD * HD];
__device__ float g_Y[BB * T_LEN * DM];
__device__ float g_bcat[4 * DM];
// packed bf16 hi/lo operands (word = bf16x2, k-pairs)
__device__ uint32_t g_Ah[BB * T_LEN * KW];     // A operand (x, later comb)
__device__ uint32_t g_Al[BB * T_LEN * KW];
__device__ uint32_t g_Wh[NWROWS * KW];         // Wq|Wk|Wv|Wg|Mi^T|Wo
__device__ uint32_t g_Wl[NWROWS * KW];

// ---------------- activations ----------------------------------------------
__device__ __forceinline__ float gelu_tanh(float x) {
    const float c0 = 0.7978845608028654f;
    float inner = c0 * (x + 0.044715f * x * x * x);
    return 0.5f * x * (1.0f + tanhf(inner));
}
__device__ __forceinline__ float sigmoidf_(float x) {
    return 1.0f / (1.0f + expf(-x));
}

// ---------------- bf16 split helpers ----------------------------------------
__device__ __forceinline__ void split2(float x0, float x1, uint32_t& hp, uint32_t& lp) {
    __nv_bfloat162 h = __floats2bfloat162_rn(x0, x1);
    float r0 = x0 - __bfloat162float(__low2bfloat16(h));
    float r1 = x1 - __bfloat162float(__high2bfloat16(h));
    __nv_bfloat162 l = __floats2bfloat162_rn(r0, r1);
    hp = *reinterpret_cast<uint32_t*>(&h);
    lp = *reinterpret_cast<uint32_t*>(&l);
}

__device__ __forceinline__ void mma16(float* d, const uint32_t* a, const uint32_t* b) {
    asm volatile(
        "mma.sync.aligned.m16n8k16.row.col.f32.bf16.bf16.f32 "
        "{%0,%1,%2,%3}, {%4,%5,%6,%7}, {%8,%9}, {%0,%1,%2,%3};"
        : "+f"(d[0]), "+f"(d[1]), "+f"(d[2]), "+f"(d[3])
        : "r"(a[0]), "r"(a[1]), "r"(a[2]), "r"(a[3]), "r"(b[0]), "r"(b[1]));
}

#define LDSM4(r0, r1, r2, r3, addr)                                            \
    asm volatile("ldmatrix.sync.aligned.m8n8.x4.shared.b16 {%0,%1,%2,%3}, [%4];" \
                 : "=r"(r0), "=r"(r1), "=r"(r2), "=r"(r3) : "r"(addr))

__device__ __forceinline__ uint32_t smem_u32(const void* p) {
    return (uint32_t)__cvta_generic_to_shared(p);
}

__device__ __forceinline__ void cp16(uint32_t dst, const void* src) {
    asm volatile("cp.async.cg.shared.global [%0], [%1], 16;" :: "r"(dst), "l"(src));
}
#define CP_COMMIT() asm volatile("cp.async.commit_group;")
#define CP_WAIT(n)  asm volatile("cp.async.wait_group %0;" :: "n"(n))

// packed fp32x2 fma (FFMA2)
__device__ __forceinline__ uint64_t fma2(uint64_t a, uint64_t b, uint64_t c) {
    uint64_t d;
    asm("fma.rn.f32x2 %0, %1, %2, %3;" : "=l"(d) : "l"(a), "l"(b), "l"(c));
    return d;
}
__device__ __forceinline__ uint64_t bcast2(float v) {
    uint64_t d;
    uint32_t bits = __float_as_uint(v);
    asm("mov.b64 %0, {%1, %1};" : "=l"(d) : "r"(bits));
    return d;
}

// ---------------- xsplit: x -> g_Ah/g_Al -------------------------------------
__global__ __launch_bounds__(256) void xsplit_kernel(const float* __restrict__ x) {
    int i = blockIdx.x * 256 + threadIdx.x;        // word index
    float2 v = reinterpret_cast<const float2*>(x)[i];
    uint32_t h, l;
    split2(v.x, v.y, h, l);
    g_Ah[i] = h;
    g_Al[i] = l;
}

// ---------------- repack+split weights: Wq|Wk|Wv|Wg|Mi^T|Wo -----------------
__global__ __launch_bounds__(256) void repack_w_kernel(const float* __restrict__ Wq,
                                                       const float* __restrict__ Wk,
                                                       const float* __restrict__ Wv,
                                                       const float* __restrict__ Wg,
                                                       const float* __restrict__ Mi,
                                                       const float* __restrict__ Wo) {
    int i = blockIdx.x * 256 + threadIdx.x;        // word index, 0..NWROWS*KW-1
    int n = i >> 8;                                // row 0..3071
    int p = i & 255;
    int k = p * 2;
    int seg = n >> 9, nn = n & (DM - 1);
    float a0, a1;
    if (seg == 4) {                                // Mi^T: row nn of Mi transpose
        a0 = Mi[(size_t)k * DM + nn];
        a1 = Mi[(size_t)(k + 1) * DM + nn];
    } else {
        const float* W = (seg == 0) ? Wq : (seg == 1) ? Wk : (seg == 2) ? Wv
                        : (seg == 3) ? Wg : Wo;
        float2 v = *reinterpret_cast<const float2*>(&W[(size_t)nn * DM + k]);
        a0 = v.x; a1 = v.y;
    }
    uint32_t h, l;
    split2(a0, a1, h, l);
    g_Wh[i] = h;
    g_Wl[i] = l;
}

// ---------------- repack biases ---------------------------------------------
__global__ __launch_bounds__(256) void repack_b_kernel(const float* __restrict__ bq,
                                                       const float* __restrict__ bk,
                                                       const float* __restrict__ bv,
                                                       const float* __restrict__ bg) {
    int i = blockIdx.x * 256 + threadIdx.x;      // 0 .. 2047
    int s2 = i >> 9, o2 = i & (DM - 1);
    const float* bp = (s2 == 0) ? bq : (s2 == 1) ? bk : (s2 == 2) ? bv : bg;
    g_bcat[i] = bp[o2];
}

// ---------------- phi_projT[r][t] = sum_k f[t][k] Mf[k][r] ------------------
__global__ __launch_bounds__(256) void phi_kernel(const float* __restrict__ f,
                                                  const float* __restrict__ Mf) {
    __shared__ float sf[KF];
    int t = blockIdx.x;
    if (threadIdx.x < KF) sf[threadIdx.x] = f[t * KF + threadIdx.x];
    __syncthreads();
    for (int r = threadIdx.x; r < DM; r += 256) {
        float acc = 0.f;
#pragma unroll
        for (int k = 0; k < KF; k++) acc += sf[k] * Mf[k * DM + r];
        g_phiT[(size_t)r * T_LEN + t] = acc;
    }
}

// ---------------- combine + split: comb = g*Y + (1-g)*xt -> g_Ah/g_Al -------
__global__ __launch_bounds__(256) void combsplit_kernel() {
    int i = blockIdx.x * 256 + threadIdx.x;        // word index
    float2 g = *reinterpret_cast<const float2*>(&g_gate[2 * i]);
    float2 y = *reinterpret_cast<const float2*>(&g_Y[2 * i]);
    float2 xt = *reinterpret_cast<const float2*>(&g_xt[2 * i]);
    float c0 = g.x * y.x + (1.f - g.x) * xt.x;
    float c1 = g.y * y.y + (1.f - g.y) * xt.y;
    uint32_t h, l;
    split2(c0, c1, h, l);
    g_Ah[i] = h;
    g_Al[i] = l;
}

// ---------------- bf16x3 tensor-core GEMM (cp.async 3-stage pipeline) --------
template <int EPI>
__device__ __forceinline__ void epi_store(int row, int col, float v,
                                          const float* bias, float* C, int N) {
    if (EPI == 0) {
        if (bias) v += bias[col];
        C[(size_t)row * N + col] = v;
    } else {
        int seg = col >> 9;
        if (seg == 4) {                       // u-projection, transposed
            g_upT[(size_t)(col - 4 * DM) * (BB * T_LEN) + row] = v;
            return;
        }
        v += g_bcat[col];
        int cc = col & (DM - 1);
        int b = row >> 10, t = row & (T_LEN - 1);
        if (seg == 3) {
            g_gate[(size_t)row * DM + cc] = sigmoidf_(v);
        } else {
            float gv = gelu_tanh(v);
            float* P = (seg == 0) ? g_Q : (seg == 1) ? g_Kb : g_V;
            P[(((size_t)(b * NH + (cc >> 6))) * T_LEN + t) * HD + (cc & 63)] = gv;
        }
    }
}

template <int BM, int EPI>
__global__ __launch_bounds__(256) void mma_gemm(const uint32_t* __restrict__ Bh,
                                                const uint32_t* __restrict__ Bl,
                                                const float* __restrict__ bias,
                                                float* __restrict__ C,
                                                int M, int N) {
    constexpr int NWM = BM / 32;           // warps along M (4 or 2)
    constexpr int NT  = NWM;               // n-subtiles per warp (4 or 2)
    constexpr int S   = 20;                // padded row stride (words)
    constexpr int STAGES = 3;
    constexpr int AOFF  = 0;
    constexpr int ALOFF = BM * S;
    constexpr int BOFF  = 2 * BM * S;
    constexpr int BLOFF = 2 * BM * S + 64 * S;
    constexpr int STW   = 2 * S * (BM + 64);   // words per stage
    constexpr int NKT   = KW / 16;             // 16 k-tiles
    extern __shared__ __align__(16) uint32_t dsm[];

    const int tid = threadIdx.x;
    const int lane = tid & 31, wid = tid >> 5;
    const int wm = wid % NWM, wn = wid / NWM;
    const int brow = blockIdx.y * BM, bcol = blockIdx.x * 64;
    const int c = lane & 3, r4 = lane >> 2;
    const uint32_t smb = smem_u32(dsm);

    // ldmatrix lane byte addresses (stage 0, ks=0)
    uint32_t oAh[2], oAl[2];
#pragma unroll
    for (int mt = 0; mt < 2; mt++) {
        int row = wm * 32 + mt * 16 + (lane & 15);
        int word = (lane & 16) >> 2;           // 0 or 4
        oAh[mt] = smb + (AOFF + row * S + word) * 4;
        oAl[mt] = smb + (ALOFF + row * S + word) * 4;
    }
    uint32_t oBh[NT / 2], oBl[NT / 2];
#pragma unroll
    for (int g = 0; g < NT / 2; g++) {
        int sel = (lane & 16) ? 1 : 0;
        int row = wn * (NT * 8) + (g * 2 + sel) * 8 + (lane & 7);
        int word = (lane & 8) ? 4 : 0;
        oBh[g] = smb + (BOFF + row * S + word) * 4;
        oBl[g] = smb + (BLOFF + row * S + word) * 4;
    }

    // cp.async tile loader
    auto load_tile = [&](int kt, int stg) {
        uint32_t sb = smb + stg * (STW * 4);
        if (BM == 128) {
            int row = tid >> 1, h8 = (tid & 1) * 8;
            size_t src = (size_t)(brow + row) * KW + kt * 16 + h8;
            uint32_t d0 = sb + (AOFF + row * S + h8) * 4;
            cp16(d0,      &g_Ah[src]);
            cp16(d0 + 16, &g_Ah[src + 4]);
            uint32_t d1 = sb + (ALOFF + row * S + h8) * 4;
            cp16(d1,      &g_Al[src]);
            cp16(d1 + 16, &g_Al[src + 4]);
        } else {
            int row = tid >> 2, q4 = (tid & 3) * 4;
            size_t src = (size_t)(brow + row) * KW + kt * 16 + q4;
            cp16(sb + (AOFF + row * S + q4) * 4,  &g_Ah[src]);
            cp16(sb + (ALOFF + row * S + q4) * 4, &g_Al[src]);
        }
        {
            int row = tid >> 2, q4 = (tid & 3) * 4;
            size_t src = (size_t)(bcol + row) * KW + kt * 16 + q4;
            cp16(sb + (BOFF + row * S + q4) * 4,  &Bh[src]);
            cp16(sb + (BLOFF + row * S + q4) * 4, &Bl[src]);
        }
    };

    float d[2][NT][4];
#pragma unroll
    for (int mt = 0; mt < 2; mt++)
#pragma unroll
        for (int nt = 0; nt < NT; nt++)
#pragma unroll
            for (int e = 0; e < 4; e++) d[mt][nt][e] = 0.f;

    // prologue: prime STAGES-1 tiles
#pragma unroll
    for (int s = 0; s < STAGES - 1; s++) { load_tile(s, s); CP_COMMIT(); }

    for (int kt = 0; kt < NKT; kt++) {
        int pf = kt + STAGES - 1;
        if (pf < NKT) load_tile(pf, pf % STAGES);
        CP_COMMIT();                       // empty group when pf >= NKT
        CP_WAIT(STAGES - 2);               // tile kt resident
        __syncthreads();

        const uint32_t so = (uint32_t)((kt % STAGES) * (STW * 4));
#pragma unroll
        for (int ks = 0; ks < 2; ks++) {
            const uint32_t kso = so + ks * 32;     // 8 words = 32 bytes
            uint32_t ah[2][4], al[2][4], bh[NT][2], bl[NT][2];
#pragma unroll
            for (int mt = 0; mt < 2; mt++) {
                LDSM4(ah[mt][0], ah[mt][1], ah[mt][2], ah[mt][3], oAh[mt] + kso);
                LDSM4(al[mt][0], al[mt][1], al[mt][2], al[mt][3], oAl[mt] + kso);
            }
#pragma unroll
            for (int g = 0; g < NT / 2; g++) {
                LDSM4(bh[2*g][0], bh[2*g][1], bh[2*g+1][0], bh[2*g+1][1], oBh[g] + kso);
                LDSM4(bl[2*g][0], bl[2*g][1], bl[2*g+1][0], bl[2*g+1][1], oBl[g] + kso);
            }
#pragma unroll
            for (int mt = 0; mt < 2; mt++)
#pragma unroll
                for (int nt = 0; nt < NT; nt++) {
                    mma16(d[mt][nt], ah[mt], bh[nt]);
                    mma16(d[mt][nt], ah[mt], bl[nt]);
                    mma16(d[mt][nt], al[mt], bh[nt]);
                }
        }
        __syncthreads();                   // protect stage buffer reuse
    }

    const int c2 = c * 2;
#pragma unroll
    for (int mt = 0; mt < 2; mt++) {
#pragma unroll
        for (int nt = 0; nt < NT; nt++) {
            int row0 = brow + wm * 32 + mt * 16 + r4;
            int col0 = bcol + wn * (NT * 8) + nt * 8 + c2;
            epi_store<EPI>(row0,     col0,     d[mt][nt][0], bias, C, N);
            epi_store<EPI>(row0,     col0 + 1, d[mt][nt][1], bias, C, N);
            epi_store<EPI>(row0 + 8, col0,     d[mt][nt][2], bias, C, N);
            epi_store<EPI>(row0 + 8, col0 + 1, d[mt][nt][3], bias, C, N);
        }
    }
}

// ---------------- conv: z[b,t,r] = 2 * sum_{j even<=t} v[j,r] u[b,t-j,r] ----
__global__ __launch_bounds__(128) void conv_kernel() {
    __shared__ __align__(16) float su[BB][T_LEN + 16];   // su[b][8+i] = u[i]
    __shared__ __align__(16) float sve[T_LEN / 2];       // sve[j/2] = v[2j]
    const int r = blockIdx.x;
    const int tid = threadIdx.x;
    const int b = tid >> 6;
    const int lt = tid & 63;
    const float* U = g_upT + (size_t)r * (BB * T_LEN) + b * T_LEN;
    const float* V = g_phiT + (size_t)r * T_LEN;
    for (int i = lt; i < T_LEN; i += 64) su[b][8 + i] = U[i];
    for (int i = tid; i < T_LEN / 2; i += 128) sve[i] = V[2 * i];
    __syncthreads();

    const int t0 = lt * 16;
    const float* sub = su[b];
    uint64_t dacc[8];
#pragma unroll
    for (int p = 0; p < 8; p++) dacc[p] = 0ull;

    const int nblk = t0 >> 3;
    if (nblk > 0) {
        uint64_t W[12];
        int base = t0;
        {
            const ulonglong2* w16 = reinterpret_cast<const ulonglong2*>(&sub[base]);
#pragma unroll
            for (int q = 0; q < 6; q++) {
                ulonglong2 u2 = w16[q];
                W[2 * q] = u2.x; W[2 * q + 1] = u2.y;
            }
        }
        for (int ib = 0; ib < nblk; ib++) {
            float4 v4 = *reinterpret_cast<const float4*>(&sve[ib * 4]);
            uint64_t vv0 = bcast2(v4.x), vv1 = bcast2(v4.y);
            uint64_t vv2 = bcast2(v4.z), vv3 = bcast2(v4.w);
#pragma unroll
            for (int p = 0; p < 8; p++) {
                dacc[p] = fma2(vv0, W[p + 4], dacc[p]);
                dacc[p] = fma2(vv1, W[p + 3], dacc[p]);
                dacc[p] = fma2(vv2, W[p + 2], dacc[p]);
                dacc[p] = fma2(vv3, W[p + 1], dacc[p]);
            }
            if (ib + 1 < nblk) {
                base -= 8;
#pragma unroll
                for (int p = 7; p >= 0; p--) W[p + 4] = W[p];
                const ulonglong2* wn = reinterpret_cast<const ulonglong2*>(&sub[base]);
                ulonglong2 a0 = wn[0], a1 = wn[1];
                W[0] = a0.x; W[1] = a0.y; W[2] = a1.x; W[3] = a1.y;
            }
        }
    }

    float acc[16];
#pragma unroll
    for (int p = 0; p < 8; p++) {
        acc[2 * p]     = __uint_as_float((uint32_t)(dacc[p] & 0xffffffffull));
        acc[2 * p + 1] = __uint_as_float((uint32_t)(dacc[p] >> 32));
    }
#pragma unroll
    for (int jo = 0; jo < 8; jo++) {
        float vj = sve[(t0 >> 1) + jo];
#pragma unroll
        for (int k = 0; k < 16; k++)
            if (k >= 2 * jo) acc[k] += vj * sub[8 + k - 2 * jo];
    }
#pragma unroll
    for (int k = 0; k < 16; k++) {
        int t = t0 + k;
        g_z[((size_t)b * T_LEN + t) * DM + r] = 2.f * acc[k];
    }
}

// ---------------- LayerNorm over last dim (512), single pass ----------------
__global__ __launch_bounds__(256) void ln_kernel(const float* __restrict__ w,
                                                 const float* __restrict__ bparm) {
    __shared__ float redA[8];
    __shared__ float redB[8];
    __shared__ float bc[2];
    int row = blockIdx.x;
    const float* xr = g_z + (size_t)row * DM;
    float v0 = xr[threadIdx.x];
    float v1 = xr[threadIdx.x + 256];
    float s1 = v0 + v1;
    float s2 = v0 * v0 + v1 * v1;
#pragma unroll
    for (int o = 16; o > 0; o >>= 1) {
        s1 += __shfl_xor_sync(0xffffffffu, s1, o);
        s2 += __shfl_xor_sync(0xffffffffu, s2, o);
    }
    int warp = threadIdx.x >> 5;
    if ((threadIdx.x & 31) == 0) { redA[warp] = s1; redB[warp] = s2; }
    __syncthreads();
    if (threadIdx.x < 32) {
        float a = (threadIdx.x < 8) ? redA[threadIdx.x] : 0.f;
        float bsum = (threadIdx.x < 8) ? redB[threadIdx.x] : 0.f;
#pragma unroll
        for (int o = 4; o > 0; o >>= 1) {
            a += __shfl_xor_sync(0xffffffffu, a, o);
            bsum += __shfl_xor_sync(0xffffffffu, bsum, o);
        }
        if (threadIdx.x == 0) { bc[0] = a; bc[1] = bsum; }
    }
    __syncthreads();
    float mu = bc[0] * (1.0f / DM);
    float var = bc[1] * (1.0f / DM) - mu * mu;
    float inv = rsqrtf(var + 1e-5f);
    float d0 = v0 - mu, d1 = v1 - mu;
    g_xt[(size_t)row * DM + threadIdx.x] = d0 * inv * w[threadIdx.x] + bparm[threadIdx.x];
    g_xt[(size_t)row * DM + threadIdx.x + 256] =
        d1 * inv * w[threadIdx.x + 256] + bparm[threadIdx.x + 256];
}

// ---------------- per-chunk state G_c = V_c^T K_c (64x64) -------------------
__global__ __launch_bounds__(256) void chunkstate_kernel() {
    __shared__ __align__(16) float sV[CHUNK * HD];
    __shared__ __align__(16) float sK[CHUNK * HD];
    int c = blockIdx.x, bh = blockIdx.y;
    const float4* Vp = reinterpret_cast<const float4*>(g_V + ((size_t)bh * T_LEN + c * CHUNK) * HD);
    const float4* Kp = reinterpret_cast<const float4*>(g_Kb + ((size_t)bh * T_LEN + c * CHUNK) * HD);
    for (int i = threadIdx.x; i < CHUNK * HD / 4; i += 256) {
        reinterpret_cast<float4*>(sV)[i] = Vp[i];
        reinterpret_cast<float4*>(sK)[i] = Kp[i];
    }
    __syncthreads();
    int p0 = (threadIdx.x >> 4) * 4, n0 = (threadIdx.x & 15) * 4;
    float acc[4][4];
#pragma unroll
    for (int i = 0; i < 4; i++)
#pragma unroll
        for (int j = 0; j < 4; j++) acc[i][j] = 0.f;
    for (int s = 0; s < CHUNK; s++) {
        float rv[4], rk[4];
#pragma unroll
        for (int i = 0; i < 4; i++) rv[i] = sV[s * HD + p0 + i];
#pragma unroll
        for (int j = 0; j < 4; j++) rk[j] = sK[s * HD + n0 + j];
#pragma unroll
        for (int i = 0; i < 4; i++)
#pragma unroll
            for (int j = 0; j < 4; j++) acc[i][j] += rv[i] * rk[j];
    }
    float* Gp = g_G + ((size_t)bh * NCHUNK + c) * HD * HD;
#pragma unroll
    for (int i = 0; i < 4; i++)
#pragma unroll
        for (int j = 0; j < 4; j++) Gp[(p0 + i) * HD + n0 + j] = acc[i][j];
}

// ---------------- exclusive prefix over chunks ------------------------------
__global__ __launch_bounds__(256) void prefix_kernel() {
    int bh = blockIdx.x;
    int base = blockIdx.y * 512;
    for (int slot = base + threadIdx.x; slot < base + 512; slot += 256) {
        float run = 0.f;
        for (int c = 0; c < NCHUNK; c++) {
            size_t idx = ((size_t)bh * NCHUNK + c) * HD * HD + slot;
            g_H[idx] = run;
            run += g_G[idx];
        }
    }
}

// ---------------- Y_c = tril(Q_c V_c^T) K_c + Q_c H_c -----------------------
__global__ __launch_bounds__(256) void attn_kernel() {
    __shared__ __align__(16) float sQ[CHUNK * HD];
    __shared__ __align__(16) float sB[CHUNK * HD];
    __shared__ __align__(16) float sS[CHUNK * CHUNK];
    int c = blockIdx.x, bh = blockIdx.y;
    int b = bh / NH, h = bh % NH;
    const float* Qp = g_Q + ((size_t)bh * T_LEN + c * CHUNK) * HD;
    const float* Vp = g_V + ((size_t)bh * T_LEN + c * CHUNK) * HD;
    const float* Kp = g_Kb + ((size_t)bh * T_LEN + c * CHUNK) * HD;

    for (int i = threadIdx.x; i < CHUNK * HD; i += 256) {
        int t = i / HD, p = i % HD;
        sQ[i] = Qp[i];
        sB[p * CHUNK + t] = Vp[i];
    }
    __syncthreads();

    int i0 = (threadIdx.x >> 4) * 4, j0 = (threadIdx.x & 15) * 4;
    float acc[4][4];
#pragma unroll
    for (int a = 0; a < 4; a++)
#pragma unroll
        for (int bb2 = 0; bb2 < 4; bb2++) acc[a][bb2] = 0.f;
    for (int p = 0; p < HD; p++) {
        float rq[4], rv[4];
#pragma unroll
        for (int a = 0; a < 4; a++) rq[a] = sQ[(i0 + a) * HD + p];
#pragma unroll
        for (int a = 0; a < 4; a++) rv[a] = sB[p * CHUNK + j0 + a];
#pragma unroll
        for (int a = 0; a < 4; a++)
#pragma unroll
            for (int bb2 = 0; bb2 < 4; bb2++) acc[a][bb2] += rq[a] * rv[bb2];
    }
#pragma unroll
    for (int a = 0; a < 4; a++)
#pragma unroll
        for (int bb2 = 0; bb2 < 4; bb2++)
            sS[(i0 + a) * CHUNK + j0 + bb2] = (j0 + bb2 <= i0 + a) ? acc[a][bb2] : 0.f;
    __syncthreads();

    for (int i = threadIdx.x; i < CHUNK * HD; i += 256) sB[i] = Kp[i];
    __syncthreads();

    float acc2[4][4];
#pragma unroll
    for (int a = 0; a < 4; a++)
#pragma unroll
        for (int bb2 = 0; bb2 < 4; bb2++) acc2[a][bb2] = 0.f;
    for (int j = 0; j < CHUNK; j++) {
        float rs[4], rk[4];
#pragma unroll
        for (int a = 0; a < 4; a++) rs[a] = sS[(i0 + a) * CHUNK + j];
#pragma unroll
        for (int a = 0; a < 4; a++) rk[a] = sB[j * HD + j0 + a];
#pragma unroll
        for (int a = 0; a < 4; a++)
#pragma unroll
            for (int bb2 = 0; bb2 < 4; bb2++) acc2[a][bb2] += rs[a] * rk[bb2];
    }
    const float* Hp = g_H + ((size_t)bh * NCHUNK + c) * HD * HD;
    for (int p = 0; p < HD; p++) {
        float rq[4], rh[4];
#pragma unroll
        for (int a = 0; a < 4; a++) rq[a] = sQ[(i0 + a) * HD + p];
#pragma unroll
        for (int a = 0; a < 4; a++) rh[a] = Hp[p * HD + j0 + a];
#pragma unroll
        for (int a = 0; a < 4; a++)
#pragma unroll
            for (int bb2 = 0; bb2 < 4; bb2++) acc2[a][bb2] += rq[a] * rh[bb2];
    }
#pragma unroll
    for (int a = 0; a < 4; a++) {
        int t = c * CHUNK + i0 + a;
#pragma unroll
        for (int bb2 = 0; bb2 < 4; bb2++)
            g_Y[((size_t)b * T_LEN + t) * DM + h * HD + j0 + bb2] = acc2[a][bb2];
    }
}

// ---------------- host launcher ---------------------------------------------
extern "C" void kernel_launch(void* const* d_in, const int* in_sizes, int n_in,
                              void* d_out, int out_size) {
    const float* x   = (const float*)d_in[0];
    const float* flt = (const float*)d_in[1];
    const float* Mi  = (const float*)d_in[2];
    const float* Mf  = (const float*)d_in[3];
    const float* Wq  = (const float*)d_in[4];
    const float* bq  = (const float*)d_in[5];
    const float* Wk  = (const float*)d_in[6];
    const float* bk  = (const float*)d_in[7];
    const float* Wv  = (const float*)d_in[8];
    const float* bv  = (const float*)d_in[9];
    const float* Wg  = (const float*)d_in[10];
    const float* bg  = (const float*)d_in[11];
    const float* Wo  = (const float*)d_in[12];
    const float* bo  = (const float*)d_in[13];
    const float* lnw = (const float*)d_in[14];
    const float* lnb = (const float*)d_in[15];
    float* out = (float*)d_out;

    uint32_t *Wh, *Wl;
    cudaGetSymbolAddress((void**)&Wh, g_Wh);
    cudaGetSymbolAddress((void**)&Wl, g_Wl);

    const int M = BB * T_LEN;  // 2048
    const int SMEM128 = 3 * 2 * 20 * (128 + 64) * 4;   // 92160 B
    const int SMEM64  = 3 * 2 * 20 * (64 + 64) * 4;    // 61440 B
    cudaFuncSetAttribute(mma_gemm<128, 1>,
                         cudaFuncAttributeMaxDynamicSharedMemorySize, SMEM128);
    cudaFuncSetAttribute(mma_gemm<64, 0>,
                         cudaFuncAttributeMaxDynamicSharedMemorySize, SMEM64);

    // 1-3: operand preparation (split once)
    xsplit_kernel<<<M * KW / 256, 256>>>(x);
    repack_w_kernel<<<NWROWS * KW / 256, 256>>>(Wq, Wk, Wv, Wg, Mi, Wo);
    repack_b_kernel<<<4 * DM / 256, 256>>>(bq, bk, bv, bg);

    // 4: fused Q|K|V|G|U projection (N = 2560)  [profiled slot]
    mma_gemm<128, 1><<<dim3(NCAT / 64, M / 128), 256, SMEM128>>>(Wh, Wl, nullptr,
                                                                 nullptr, M, NCAT);

    // 5-7: STU branch
    phi_kernel<<<T_LEN, 256>>>(flt, Mf);
    conv_kernel<<<DM, 128>>>();
    ln_kernel<<<M, 256>>>(lnw, lnb);

    // 8-10: chunked linear attention
    chunkstate_kernel<<<dim3(NCHUNK, NBH), 256>>>();
    prefix_kernel<<<dim3(NBH, 8), 256>>>();
    attn_kernel<<<dim3(NCHUNK, NBH), 256>>>();

    // 11: combine + split into A buffers
    combsplit_kernel<<<M * KW / 256, 256>>>();

    // 12: output projection (B = Wo rows at offset NCAT)
    mma_gemm<64, 0><<<dim3(DM / 64, M / 64), 256, SMEM64>>>(Wh + (size_t)NCAT * KW,
                                                            Wl + (size_t)NCAT * KW,
                                                            bo, out, M, DM);
}